// round 7
// baseline (speedup 1.0000x reference)
#include <cuda_runtime.h>

// RoiPoolingConv: bilinear 7x7 ROI pooling over NHWC feat (1,200,200,512) fp32.
// out shape (1, 300, 7, 7, 512) fp32.
//
// d_in[0]: feat  float32  [1,200,200,512]
// d_in[1]: rois  int32    [1,300,4]  (x0, y0, w, h)
//
// R7: persistence x low-registers. Plain grid-stride loop over cells with the
//     exact R4 per-thread body (4x LDG.128, blend, STG.128) and no software
//     pipelining, so regs stay ~32 and occupancy ~80% while CTA setup/drain
//     churn (99 CTA launches per SM) is removed.

#define POOL 7
#define NUM_ROIS 300
#define FH 200
#define FW 200
#define FC 512
#define TOTAL_CELLS (NUM_ROIS * POOL * POOL)   // 14700
#define NBLOCKS (148 * 12)                     // 1776 persistent CTAs, ~8 iters

__global__ __launch_bounds__(128, 8)
void roi_pool_kernel(const float* __restrict__ feat,
                     const int* __restrict__ rois,
                     float* __restrict__ out) {
    const int c4 = threadIdx.x;   // channel quad 0..127

    for (int idx = blockIdx.x; idx < TOTAL_CELLS; idx += NBLOCKS) {
        const int roi  = idx / (POOL * POOL);
        const int cell = idx - roi * (POOL * POOL);
        const int py = cell / POOL;
        const int px = cell - py * POOL;

        const int4 r = __ldg(((const int4*)rois) + roi);
        const int x0 = r.x, y0 = r.y, w = r.z, h = r.w;

        // Match reference math exactly:
        //   sy = py * (h/7), y_lo = floor(sy), y_hi = min(y_lo+1, h-1), fy = sy - y_lo
        const float sy = (float)py * ((float)h / (float)POOL);
        const float sx = (float)px * ((float)w / (float)POOL);
        const int y_lo = (int)floorf(sy);
        const int x_lo = (int)floorf(sx);
        const int y_hi = min(y_lo + 1, h - 1);
        const int x_hi = min(x_lo + 1, w - 1);
        const float fy = sy - (float)y_lo;
        const float fx = sx - (float)x_lo;

        const int ay_lo = y0 + y_lo, ay_hi = y0 + y_hi;
        const int ax_lo = x0 + x_lo, ax_hi = x0 + x_hi;

        // Channel-contiguous NHWC: feat[(y*FW + x)*FC + c]
        const float4* p00 = (const float4*)(feat + ((size_t)ay_lo * FW + ax_lo) * FC);
        const float4* p01 = (const float4*)(feat + ((size_t)ay_lo * FW + ax_hi) * FC);
        const float4* p10 = (const float4*)(feat + ((size_t)ay_hi * FW + ax_lo) * FC);
        const float4* p11 = (const float4*)(feat + ((size_t)ay_hi * FW + ax_hi) * FC);

        // 4 independent 16B loads in flight per thread.
        const float4 v00 = __ldg(p00 + c4);
        const float4 v01 = __ldg(p01 + c4);
        const float4 v10 = __ldg(p10 + c4);
        const float4 v11 = __ldg(p11 + c4);

        const float gx = 1.0f - fx;
        const float gy = 1.0f - fy;

        float4 o;
        {
            float top, bot;
            top = v00.x * gx + v01.x * fx;
            bot = v10.x * gx + v11.x * fx;
            o.x = top * gy + bot * fy;
            top = v00.y * gx + v01.y * fx;
            bot = v10.y * gx + v11.y * fx;
            o.y = top * gy + bot * fy;
            top = v00.z * gx + v01.z * fx;
            bot = v10.z * gx + v11.z * fx;
            o.z = top * gy + bot * fy;
            top = v00.w * gx + v01.w * fx;
            bot = v10.w * gx + v11.w * fx;
            o.w = top * gy + bot * fy;
        }

        // Streaming store: evict-first in L2, keep feat resident.
        float4* outp = (float4*)(out + (size_t)idx * FC);
        __stcs(outp + c4, o);
    }
}

extern "C" void kernel_launch(void* const* d_in, const int* in_sizes, int n_in,
                              void* d_out, int out_size) {
    const float* feat = (const float*)d_in[0];
    const int*   rois = (const int*)d_in[1];
    float*       out  = (float*)d_out;

    roi_pool_kernel<<<NBLOCKS, 128>>>(feat, rois, out);
}